// round 6
// baseline (speedup 1.0000x reference)
#include <cuda_runtime.h>

// FocalLoss: loss = sum_b mean_a [ w[a] * (1-p)^2 * BCE(clamp(p), t) ]
// inputs [B, A] f32, targets [A, B] i32 (0/1), w [A] f32 -> scalar f32
// 4 consecutive b per thread: targets load as int4, inputs as float4 ->
// 20 LDG/thread/b (vs 50), all 128-bit, 8-wide MLP per a4 step.
constexpr int BVAL = 1000000;
constexpr int AVAL = 40;
constexpr float EPSF = 1e-12f;
constexpr int TPB = 256;
constexpr int B4 = BVAL / 4;                   // 250000 thread-groups
constexpr int GRID = (B4 + TPB - 1) / TPB;     // 977
constexpr int PARTIALS_PAD = 1024;             // 256 threads * 1 float4

__device__ float g_partials[PARTIALS_PAD];     // zero-init; [GRID,1024) never written

__global__ void __launch_bounds__(TPB) focal_main_kernel(
    const float* __restrict__ inputs,
    const int*   __restrict__ targets,
    const float* __restrict__ w)
{
    __shared__ float sw[AVAL];
    int tid = threadIdx.x;
    if (tid < AVAL) sw[tid] = w[tid];
    __syncthreads();

    int g = blockIdx.x * TPB + tid;   // group of 4 consecutive b
    float acc = 0.0f;
    if (g < B4) {
        long b0 = (long)g * 4;
        const float4* in4 = reinterpret_cast<const float4*>(inputs);   // idx = b*10 + a4
        const int4*   tg4 = reinterpret_cast<const int4*>(targets);    // idx = (a*B + b)/4

        #pragma unroll
        for (int a4 = 0; a4 < AVAL / 4; a4++) {
            // 4 input float4: rows b0..b0+3 at column block a4 (independent loads)
            float4 q0 = __ldg(in4 + (b0 + 0) * (AVAL / 4) + a4);
            float4 q1 = __ldg(in4 + (b0 + 1) * (AVAL / 4) + a4);
            float4 q2 = __ldg(in4 + (b0 + 2) * (AVAL / 4) + a4);
            float4 q3 = __ldg(in4 + (b0 + 3) * (AVAL / 4) + a4);
            // 4 target int4: attrs a4*4..+3, each covering b0..b0+3 (lane-contiguous)
            int4 t0 = __ldg(tg4 + ((long)(a4 * 4 + 0) * BVAL + b0) / 4);
            int4 t1 = __ldg(tg4 + ((long)(a4 * 4 + 1) * BVAL + b0) / 4);
            int4 t2 = __ldg(tg4 + ((long)(a4 * 4 + 2) * BVAL + b0) / 4);
            int4 t3 = __ldg(tg4 + ((long)(a4 * 4 + 3) * BVAL + b0) / 4);

            float pv[4][4] = {{q0.x, q0.y, q0.z, q0.w},
                              {q1.x, q1.y, q1.z, q1.w},
                              {q2.x, q2.y, q2.z, q2.w},
                              {q3.x, q3.y, q3.z, q3.w}};
            int   tv[4][4] = {{t0.x, t0.y, t0.z, t0.w},    // tv[j][r]: attr j, row r
                              {t1.x, t1.y, t1.z, t1.w},
                              {t2.x, t2.y, t2.z, t2.w},
                              {t3.x, t3.y, t3.z, t3.w}};

            #pragma unroll
            for (int j = 0; j < 4; j++) {
                float wj = sw[a4 * 4 + j];
                #pragma unroll
                for (int r = 0; r < 4; r++) {
                    float p  = pv[r][j];
                    float pc = fminf(fmaxf(p, EPSF), 1.0f - EPSF);
                    float arg = tv[j][r] ? pc : (1.0f - pc);  // t is 0/1: one log
                    float bce = -__logf(arg);                 // MUFU.LG2
                    float om  = 1.0f - p;                     // unclamped p
                    acc = fmaf(wj * om * om, bce, acc);
                }
            }
        }
    }

    // intra-warp reduce
    #pragma unroll
    for (int off = 16; off; off >>= 1)
        acc += __shfl_down_sync(0xffffffffu, acc, off);

    __shared__ float warpsum[TPB / 32];
    if ((tid & 31) == 0) warpsum[tid >> 5] = acc;
    __syncthreads();

    if (tid == 0) {
        float v = 0.0f;
        #pragma unroll
        for (int i = 0; i < TPB / 32; i++) v += warpsum[i];
        g_partials[blockIdx.x] = v;   // plain store, overwritten every launch
    }
}

__global__ void __launch_bounds__(TPB) finalize_kernel(float* __restrict__ out)
{
    int tid = threadIdx.x;
    const float4* p4 = reinterpret_cast<const float4*>(g_partials);
    float4 v = p4[tid];   // 1024 floats total, one float4 per thread
    double d = ((double)v.x + v.y) + ((double)v.z + v.w);

    #pragma unroll
    for (int off = 16; off; off >>= 1)
        d += __shfl_down_sync(0xffffffffu, d, off);

    __shared__ double dws[TPB / 32];
    if ((tid & 31) == 0) dws[tid >> 5] = d;
    __syncthreads();
    if (tid == 0) {
        double tot = 0.0;
        #pragma unroll
        for (int i = 0; i < TPB / 32; i++) tot += dws[i];
        out[0] = (float)(tot * (1.0 / (double)AVAL));
    }
}

extern "C" void kernel_launch(void* const* d_in, const int* in_sizes, int n_in,
                              void* d_out, int out_size)
{
    const float* inputs  = (const float*)d_in[0];   // [B, A]
    const int*   targets = (const int*)  d_in[1];   // [A, B]
    const float* weights = (const float*)d_in[2];   // [A]
    focal_main_kernel<<<GRID, TPB>>>(inputs, targets, weights);
    finalize_kernel<<<1, TPB>>>((float*)d_out);
}

// round 7
// speedup vs baseline: 2.0022x; 2.0022x over previous
#include <cuda_runtime.h>

// FocalLoss: loss = sum_b mean_a [ w[a] * (1-p)^2 * BCE(clamp(p), t) ]
// inputs [B, A] f32, targets [A, B] i32 (0/1), w [A] f32 -> scalar f32
//
// R1 (measured best, 55.8us) mainloop byte-for-byte: thread-per-b, float4
// input row loads, lane-coalesced target loads, one MUFU log per element,
// block result via atomicAdd(double). Only change vs R1: the zero kernel is
// gone -- finalize reads g_acc, writes out, and RESETS g_acc to 0 so the
// next graph replay starts clean. 2 graph nodes instead of 3.
constexpr int BVAL = 1000000;
constexpr int AVAL = 40;
constexpr float EPSF = 1e-12f;
constexpr int TPB = 256;
constexpr int GRID = (BVAL + TPB - 1) / TPB;   // 3907

__device__ double g_acc;   // zero at module load; reset by finalize each launch

__global__ void __launch_bounds__(TPB) focal_main_kernel(
    const float* __restrict__ inputs,
    const int*   __restrict__ targets,
    const float* __restrict__ w)
{
    __shared__ float sw[AVAL];
    int tid = threadIdx.x;
    if (tid < AVAL) sw[tid] = w[tid];
    __syncthreads();

    int b = blockIdx.x * TPB + tid;
    float acc = 0.0f;
    if (b < BVAL) {
        const float4* row = reinterpret_cast<const float4*>(inputs + (long)b * AVAL);
        #pragma unroll
        for (int a4 = 0; a4 < AVAL / 4; a4++) {
            float4 p4 = __ldg(row + a4);
            float pv[4] = {p4.x, p4.y, p4.z, p4.w};
            #pragma unroll
            for (int j = 0; j < 4; j++) {
                int a = a4 * 4 + j;
                int t = __ldg(targets + (long)a * BVAL + b);  // coalesced per a
                float p  = pv[j];
                float pc = fminf(fmaxf(p, EPSF), 1.0f - EPSF);
                float arg = t ? pc : (1.0f - pc);   // t is 0/1: one log suffices
                float bce = -__logf(arg);           // MUFU.LG2 path
                float om  = 1.0f - p;               // focal weight uses UNCLAMPED p
                acc = fmaf(sw[a] * om * om, bce, acc);
            }
        }
    }

    // warp reduce
    #pragma unroll
    for (int off = 16; off; off >>= 1)
        acc += __shfl_down_sync(0xffffffffu, acc, off);

    __shared__ float warpsum[TPB / 32];
    if ((tid & 31) == 0) warpsum[tid >> 5] = acc;
    __syncthreads();

    if (tid < TPB / 32) {
        float v = warpsum[tid];
        #pragma unroll
        for (int off = (TPB / 64); off; off >>= 1)
            v += __shfl_down_sync(0xffu, v, off);
        if (tid == 0) atomicAdd(&g_acc, (double)v);
    }
}

__global__ void finalize_kernel(float* __restrict__ out) {
    out[0] = (float)(g_acc * (1.0 / (double)AVAL));
    g_acc = 0.0;   // self-reset: next replay starts from zero, no init kernel
}

extern "C" void kernel_launch(void* const* d_in, const int* in_sizes, int n_in,
                              void* d_out, int out_size)
{
    const float* inputs  = (const float*)d_in[0];   // [B, A]
    const int*   targets = (const int*)  d_in[1];   // [A, B]
    const float* weights = (const float*)d_in[2];   // [A]

    focal_main_kernel<<<GRID, TPB>>>(inputs, targets, weights);
    finalize_kernel<<<1, 1>>>((float*)d_out);
}

// round 8
// speedup vs baseline: 2.1213x; 1.0595x over previous
#include <cuda_runtime.h>
#include <cstdint>

// FocalLoss: loss = sum_b mean_a [ w[a] * (1-p)^2 * BCE(clamp(p), t) ]
// inputs [B, A] f32, targets [A, B] i32 (0/1), w [A] f32 -> scalar f32
//
// Mainloop change vs R1/R6: input rows are staged through shared memory with
// lane-contiguous cp.async 16B copies (4 L1tex wavefronts/inst instead of 32
// for the old 160B-lane-stride LDG.128), then read per-row via LDS.128.
// Targets remain direct coalesced LDG.32. Tail: atomicAdd(double) +
// self-resetting finalize (2 graph nodes).
constexpr int BVAL = 1000000;
constexpr int AVAL = 40;
constexpr float EPSF = 1e-12f;
constexpr int TPB = 256;
constexpr int GRID = (BVAL + TPB - 1) / TPB;        // 3907
constexpr int ROW_F4 = AVAL / 4;                    // 10 float4 per row
constexpr int TILE_F4 = TPB * ROW_F4;               // 2560 float4 per block
constexpr long TOTAL_F4 = (long)BVAL * ROW_F4;      // 10e6

__device__ double g_acc;   // zero at module load; reset by finalize each launch

__device__ __forceinline__ uint32_t smem_u32(const void* p) {
    uint32_t a;
    asm("{ .reg .u64 t; cvta.to.shared.u64 t, %1; cvt.u32.u64 %0, t; }"
        : "=r"(a) : "l"(p));
    return a;
}

__global__ void __launch_bounds__(TPB) focal_main_kernel(
    const float* __restrict__ inputs,
    const int*   __restrict__ targets,
    const float* __restrict__ w)
{
    __shared__ float4 s4[TILE_F4];     // 40 KB: block's 256 input rows
    __shared__ float  sw[AVAL];

    int tid = threadIdx.x;
    if (tid < AVAL) sw[tid] = w[tid];

    // Stage the block's input slab: lane-contiguous 16B async copies.
    long base_f4 = (long)blockIdx.x * TILE_F4;
    const float4* in4 = reinterpret_cast<const float4*>(inputs);
    #pragma unroll
    for (int i = 0; i < ROW_F4; i++) {
        int  sidx = tid + i * TPB;
        long gidx = base_f4 + sidx;
        if (gidx < TOTAL_F4) {
            uint32_t dst = smem_u32(&s4[sidx]);
            asm volatile("cp.async.cg.shared.global [%0], [%1], 16;"
                         :: "r"(dst), "l"(in4 + gidx) : "memory");
        } else {
            s4[sidx] = make_float4(0.f, 0.f, 0.f, 0.f);
        }
    }
    asm volatile("cp.async.commit_group;" ::: "memory");
    asm volatile("cp.async.wait_group 0;" ::: "memory");
    __syncthreads();

    int b = blockIdx.x * TPB + tid;
    float acc = 0.0f;
    if (b < BVAL) {
        #pragma unroll
        for (int a4 = 0; a4 < ROW_F4; a4++) {
            float4 p4 = s4[tid * ROW_F4 + a4];          // own row from smem
            float pv[4] = {p4.x, p4.y, p4.z, p4.w};
            #pragma unroll
            for (int j = 0; j < 4; j++) {
                int a = a4 * 4 + j;
                int t = __ldg(targets + (long)a * BVAL + b);  // coalesced per a
                float p  = pv[j];
                float pc = fminf(fmaxf(p, EPSF), 1.0f - EPSF);
                float arg = t ? pc : (1.0f - pc);   // t is 0/1: one log suffices
                float bce = -__logf(arg);           // MUFU.LG2 path
                float om  = 1.0f - p;               // focal weight uses UNCLAMPED p
                acc = fmaf(sw[a] * om * om, bce, acc);
            }
        }
    }

    // warp reduce
    #pragma unroll
    for (int off = 16; off; off >>= 1)
        acc += __shfl_down_sync(0xffffffffu, acc, off);

    __shared__ float warpsum[TPB / 32];
    if ((tid & 31) == 0) warpsum[tid >> 5] = acc;
    __syncthreads();

    if (tid < TPB / 32) {
        float v = warpsum[tid];
        #pragma unroll
        for (int off = (TPB / 64); off; off >>= 1)
            v += __shfl_down_sync(0xffu, v, off);
        if (tid == 0) atomicAdd(&g_acc, (double)v);
    }
}

__global__ void finalize_kernel(float* __restrict__ out) {
    out[0] = (float)(g_acc * (1.0 / (double)AVAL));
    g_acc = 0.0;   // self-reset: next graph replay starts from zero
}

extern "C" void kernel_launch(void* const* d_in, const int* in_sizes, int n_in,
                              void* d_out, int out_size)
{
    const float* inputs  = (const float*)d_in[0];   // [B, A]
    const int*   targets = (const int*)  d_in[1];   // [A, B]
    const float* weights = (const float*)d_in[2];   // [A]

    focal_main_kernel<<<GRID, TPB>>>(inputs, targets, weights);
    finalize_kernel<<<1, 1>>>((float*)d_out);
}